// round 1
// baseline (speedup 1.0000x reference)
#include <cuda_runtime.h>
#include <math.h>

#define NVERT 300000
#define NPOS  500000

// ---------------- device scratch (no allocs allowed) ----------------
__device__ float  g_x1[NVERT * 64];    // layer0 output (pre-GN1 stats)
__device__ float  g_x2[NVERT * 32];    // layer1 output
__device__ float  g_x3[NVERT * 8];     // layer2 output (bottleneck)
__device__ float  g_proj[NVERT * 20];  // lv @ cls_W^T
__device__ double g_acc[320];          // [0,128): L0 sum/sq, [128,256): L1, [256,320): L2
__device__ float  g_scale[160];        // [0,64) L0, [64,128) L1, [128,160) L2
__device__ float  g_shift[160];

// ---------------- init ----------------
__global__ void init_acc_kernel() {
    int i = threadIdx.x;
    if (i < 320) g_acc[i] = 0.0;
}

// ---------------- per-channel stats (sum, sumsq) ----------------
template <int C>
__global__ void stats_kernel(const float* __restrict__ X, double* __restrict__ acc, int nrows) {
    __shared__ double ssum[C];
    __shared__ double ssq[C];
    int tid = threadIdx.x;
    for (int i = tid; i < C; i += blockDim.x) { ssum[i] = 0.0; ssq[i] = 0.0; }
    __syncthreads();

    long long total  = (long long)nrows * C;
    long long start  = (long long)blockIdx.x * blockDim.x + tid;
    long long stride = (long long)gridDim.x * blockDim.x;   // divisible by C (C | 256*grid)
    int c = (int)(start % C);

    double ls = 0.0, lq = 0.0;
    for (long long i = start; i < total; i += stride) {
        float v = X[i];
        ls += (double)v;
        lq += (double)v * (double)v;
    }
    atomicAdd(&ssum[c], ls);
    atomicAdd(&ssq[c], lq);
    __syncthreads();
    for (int i = tid; i < C; i += blockDim.x) {
        atomicAdd(&acc[i], ssum[i]);
        atomicAdd(&acc[C + i], ssq[i]);
    }
}

// ---------------- stats -> per-channel affine (GN folded) ----------------
template <int C>
__global__ void finalize_kernel(const double* __restrict__ acc,
                                const float* __restrict__ w, const float* __restrict__ b,
                                float* __restrict__ scale, float* __restrict__ shift, int nrows) {
    int c = threadIdx.x;
    if (c >= C) return;
    constexpr int CPG = C / 32;   // channels per group (32 groups)
    int g = c / CPG;
    double s = 0.0, q = 0.0;
#pragma unroll
    for (int j = 0; j < CPG; j++) {
        s += acc[g * CPG + j];
        q += acc[C + g * CPG + j];
    }
    double n   = (double)nrows * (double)CPG;
    double mu  = s / n;
    double var = q / n - mu * mu;
    float  rs  = (float)(1.0 / sqrt(var + 1e-5));
    float  sc  = w[c] * rs;
    scale[c] = sc;
    shift[c] = b[c] - (float)mu * sc;
}

// ---------------- tiled GEMM: Y[r,o] = sum_i f(X[r,i]) * W[o,i] ----------------
// f = relu(x*scale+shift) if AFF else identity. W is [COUT, CIN] row-major.
template <int CIN, int COUT, bool AFF>
__global__ void layer_kernel(const float* __restrict__ X, const float* __restrict__ W,
                             const float* __restrict__ scale, const float* __restrict__ shift,
                             float* __restrict__ Y, int nrows) {
    constexpr int TR  = 64;       // rows per block
    constexpr int PAD = 4;
    __shared__ float sA[TR][CIN + PAD];
    __shared__ float sW[COUT][CIN + PAD];

    int tid = threadIdx.x;        // 256 threads

    // load W into shared
    for (int i = tid; i < COUT * CIN; i += 256) {
        int o = i / CIN, c = i % CIN;
        sW[o][c] = W[i];
    }

    int row0 = blockIdx.x * TR;
    // stage A tile (affine + relu applied on load)
    for (int i = tid * 4; i < TR * CIN; i += 256 * 4) {
        int r = i / CIN, c = i % CIN;
        float4 v;
        if (row0 + r < nrows) {
            v = *(const float4*)&X[(size_t)(row0 + r) * CIN + c];
        } else {
            v = make_float4(0.f, 0.f, 0.f, 0.f);
        }
        if (AFF) {
            v.x = fmaxf(fmaf(v.x, scale[c + 0], shift[c + 0]), 0.f);
            v.y = fmaxf(fmaf(v.y, scale[c + 1], shift[c + 1]), 0.f);
            v.z = fmaxf(fmaf(v.z, scale[c + 2], shift[c + 2]), 0.f);
            v.w = fmaxf(fmaf(v.w, scale[c + 3], shift[c + 3]), 0.f);
        }
        *(float4*)&sA[r][c] = v;
    }
    __syncthreads();

    int r     = tid >> 2;     // 0..63
    int olane = tid & 3;      // 0..3
    constexpr int NO = COUT / 4;
    float acc[NO];
#pragma unroll
    for (int k = 0; k < NO; k++) acc[k] = 0.f;

#pragma unroll 4
    for (int i4 = 0; i4 < CIN; i4 += 4) {
        float4 a = *(float4*)&sA[r][i4];
#pragma unroll
        for (int k = 0; k < NO; k++) {
            int o = olane + 4 * k;
            float4 w4 = *(float4*)&sW[o][i4];
            acc[k] = fmaf(a.x, w4.x, acc[k]);
            acc[k] = fmaf(a.y, w4.y, acc[k]);
            acc[k] = fmaf(a.z, w4.z, acc[k]);
            acc[k] = fmaf(a.w, w4.w, acc[k]);
        }
    }

    if (row0 + r < nrows) {
#pragma unroll
        for (int k = 0; k < NO; k++)
            Y[(size_t)(row0 + r) * COUT + olane + 4 * k] = acc[k];
    }
}

// ---------------- per-position epilogue ----------------
__global__ void final_kernel(const int* __restrict__ idx, const float* __restrict__ bary,
                             const float* __restrict__ x3, const float* __restrict__ proj,
                             const float* __restrict__ gamma, const float* __restrict__ beta,
                             const float* __restrict__ dWw, const float* __restrict__ dWb,
                             const float* __restrict__ clsb, float* __restrict__ out, int npos) {
    int p = blockIdx.x * blockDim.x + threadIdx.x;
    if (p >= npos) return;

    int4   vi = ((const int4*)idx)[p];
    float4 vb = ((const float4*)bary)[p];
    int   ivs[4] = {vi.x, vi.y, vi.z, vi.w};
    float bb[4]  = {vb.x, vb.y, vb.z, vb.w};

    float row[4][9];
#pragma unroll
    for (int v = 0; v < 4; v++) {
        const float4* xp = (const float4*)(x3 + (size_t)ivs[v] * 8);
        float4 a = __ldg(xp);
        float4 b = __ldg(xp + 1);
        row[v][0] = a.x; row[v][1] = a.y; row[v][2] = a.z; row[v][3] = a.w;
        row[v][4] = b.x; row[v][5] = b.y; row[v][6] = b.z; row[v][7] = b.w;
        row[v][8] = bb[v];
    }

    float wv[4];
    float db = __ldg(dWb);
#pragma unroll
    for (int v = 0; v < 4; v++) wv[v] = db;

#pragma unroll
    for (int j = 0; j < 9; j++) {
        float m   = fmaxf(fmaxf(row[0][j], row[1][j]), fmaxf(row[2][j], row[3][j]));
        float off = fmaf(__ldg(&gamma[j]), m, __ldg(&beta[j]));
        float dw  = __ldg(&dWw[j]);
#pragma unroll
        for (int v = 0; v < 4; v++) wv[v] = fmaf(row[v][j] - off, dw, wv[v]);
    }
#pragma unroll
    for (int v = 0; v < 4; v++) wv[v] += bb[v];

    float o[20];
#pragma unroll
    for (int c = 0; c < 20; c++) o[c] = __ldg(&clsb[c]);

#pragma unroll
    for (int v = 0; v < 4; v++) {
        const float4* pr = (const float4*)(proj + (size_t)ivs[v] * 20);
        float w = wv[v];
#pragma unroll
        for (int k = 0; k < 5; k++) {
            float4 q = __ldg(pr + k);
            o[4 * k + 0] = fmaf(w, q.x, o[4 * k + 0]);
            o[4 * k + 1] = fmaf(w, q.y, o[4 * k + 1]);
            o[4 * k + 2] = fmaf(w, q.z, o[4 * k + 2]);
            o[4 * k + 3] = fmaf(w, q.w, o[4 * k + 3]);
        }
    }

    float4* op = (float4*)(out + (size_t)p * 20);
#pragma unroll
    for (int k = 0; k < 5; k++)
        op[k] = make_float4(o[4 * k], o[4 * k + 1], o[4 * k + 2], o[4 * k + 3]);
}

// ---------------- launch ----------------
extern "C" void kernel_launch(void* const* d_in, const int* in_sizes, int n_in,
                              void* d_out, int out_size) {
    const float* lv    = (const float*)d_in[0];
    // d_in[1] = positions (unused by the reference computation)
    const int*   idx   = (const int*)d_in[2];
    const float* bary  = (const float*)d_in[3];
    const float* gn0_w = (const float*)d_in[4];
    const float* gn0_b = (const float*)d_in[5];
    const float* W0    = (const float*)d_in[6];
    const float* gn1_w = (const float*)d_in[7];
    const float* gn1_b = (const float*)d_in[8];
    const float* W1    = (const float*)d_in[9];
    const float* gn2_w = (const float*)d_in[10];
    const float* gn2_b = (const float*)d_in[11];
    const float* W2    = (const float*)d_in[12];
    const float* gamma = (const float*)d_in[13];
    const float* beta  = (const float*)d_in[14];
    const float* dW_W  = (const float*)d_in[15];
    const float* dW_b  = (const float*)d_in[16];
    const float* clsW  = (const float*)d_in[17];
    const float* clsb  = (const float*)d_in[18];
    float* out = (float*)d_out;

    float*  x1;   cudaGetSymbolAddress((void**)&x1,   g_x1);
    float*  x2;   cudaGetSymbolAddress((void**)&x2,   g_x2);
    float*  x3;   cudaGetSymbolAddress((void**)&x3,   g_x3);
    float*  proj; cudaGetSymbolAddress((void**)&proj, g_proj);
    double* acc;  cudaGetSymbolAddress((void**)&acc,  g_acc);
    float*  scl;  cudaGetSymbolAddress((void**)&scl,  g_scale);
    float*  shf;  cudaGetSymbolAddress((void**)&shf,  g_shift);

    const int gl = (NVERT + 63) / 64;       // layer grid
    const int gs = 1184;                    // stats grid (8 blocks/SM)

    init_acc_kernel<<<1, 320>>>();

    // ---- stage 0: GN stats of lv, layer0 GEMM ----
    stats_kernel<64><<<gs, 256>>>(lv, acc, NVERT);
    finalize_kernel<64><<<1, 64>>>(acc, gn0_w, gn0_b, scl, shf, NVERT);
    layer_kernel<64, 64, true><<<gl, 256>>>(lv, W0, scl, shf, x1, NVERT);

    // ---- stage 1 ----
    stats_kernel<64><<<gs, 256>>>(x1, acc + 128, NVERT);
    finalize_kernel<64><<<1, 64>>>(acc + 128, gn1_w, gn1_b, scl + 64, shf + 64, NVERT);
    layer_kernel<64, 32, true><<<gl, 256>>>(x1, W1, scl + 64, shf + 64, x2, NVERT);

    // ---- stage 2 (bottleneck) ----
    stats_kernel<32><<<gs, 256>>>(x2, acc + 256, NVERT);
    finalize_kernel<32><<<1, 32>>>(acc + 256, gn2_w, gn2_b, scl + 128, shf + 128, NVERT);
    layer_kernel<32, 8, true><<<gl, 256>>>(x2, W2, scl + 128, shf + 128, x3, NVERT);

    // ---- proj = lv @ cls_W^T (classify pushed before the gather by linearity) ----
    layer_kernel<64, 20, false><<<gl, 256>>>(lv, clsW, nullptr, nullptr, proj, NVERT);

    // ---- per-position gather + simplex norm + delta weights + classify ----
    final_kernel<<<(NPOS + 255) / 256, 256>>>(idx, bary, x3, proj, gamma, beta,
                                              dW_W, dW_b, clsb, out, NPOS);
}

// round 2
// speedup vs baseline: 2.3976x; 2.3976x over previous
#include <cuda_runtime.h>
#include <math.h>

#define NVERT 300000
#define NPOS  500000

// ---------------- device scratch (no allocs allowed) ----------------
__device__ float  g_x1[NVERT * 64];
__device__ float  g_x2[NVERT * 32];
__device__ float  g_x3[NVERT * 8];
__device__ float  g_proj[NVERT * 20];
__device__ double g_acc[320];          // stage0 @0, stage1 @128, stage2 @256 (sum|sumsq)
__device__ float  g_scale[160];
__device__ float  g_shift[160];

__global__ void init_acc_kernel() {
    int i = threadIdx.x;
    if (i < 320) g_acc[i] = 0.0;
}

// ---------------- stats -> per-channel affine (GN folded) ----------------
template <int C>
__global__ void finalize_kernel(const double* __restrict__ acc,
                                const float* __restrict__ w, const float* __restrict__ b,
                                float* __restrict__ scale, float* __restrict__ shift, int nrows) {
    int c = threadIdx.x;
    if (c >= C) return;
    constexpr int CPG = C / 32;
    int g = c / CPG;
    double s = 0.0, q = 0.0;
#pragma unroll
    for (int j = 0; j < CPG; j++) {
        s += acc[g * CPG + j];
        q += acc[C + g * CPG + j];
    }
    double n   = (double)nrows * (double)CPG;
    double mu  = s / n;
    double var = q / n - mu * mu;
    float  rs  = (float)(1.0 / sqrt(var + 1e-5));
    float  sc  = w[c] * rs;
    scale[c] = sc;
    shift[c] = b[c] - (float)mu * sc;
}

// =====================================================================
// WIDE layers: CIN=64, COUT = 32*CPL (64 or 32). Always affine+relu in.
// Warp lanes -> output cols (strided conflict-free W reads),
// A reads warp-uniform broadcasts. Thread tile: 16 rows x CPL cols.
// Optionally accumulates output channel stats (for the next GN).
// =====================================================================
template <int CPL, bool STATS>
__global__ void __launch_bounds__(256)
layer_wide_kernel(const float* __restrict__ X, const float* __restrict__ W,
                  const float* __restrict__ scale, const float* __restrict__ shift,
                  float* __restrict__ Y, double* __restrict__ accout, int nrows) {
    constexpr int CIN = 64, LDA = 68, COUT = 32 * CPL, TRW = 128;
    extern __shared__ float sm[];
    float* sA = sm;                   // [TRW][LDA]
    float* sW = sA + TRW * LDA;       // [COUT][LDA]
    float* sS = sW + COUT * LDA;      // [2*COUT]
    int tid = threadIdx.x, lane = tid & 31, wid = tid >> 5;
    int row0 = blockIdx.x * TRW;

    // stage W
    for (int i = tid * 4; i < COUT * CIN; i += 1024) {
        int o = i >> 6, c = i & 63;
        *(float4*)&sW[o * LDA + c] = *(const float4*)&W[i];
    }
    if (STATS) {
        for (int i = tid; i < 2 * COUT; i += 256) sS[i] = 0.f;
    }

    // stage A with fused affine+relu (channel of each thread's chunks is fixed)
    int c0 = (tid * 4) & 63;
    float4 sc4 = *(const float4*)&scale[c0];
    float4 sh4 = *(const float4*)&shift[c0];
    for (int i = tid * 4; i < TRW * CIN; i += 1024) {
        int r = i >> 6, c = i & 63;
        float4 v = make_float4(0.f, 0.f, 0.f, 0.f);
        if (row0 + r < nrows) v = *(const float4*)&X[(size_t)(row0 + r) * 64 + c];
        v.x = fmaxf(fmaf(v.x, sc4.x, sh4.x), 0.f);
        v.y = fmaxf(fmaf(v.y, sc4.y, sh4.y), 0.f);
        v.z = fmaxf(fmaf(v.z, sc4.z, sh4.z), 0.f);
        v.w = fmaxf(fmaf(v.w, sc4.w, sh4.w), 0.f);
        *(float4*)&sA[r * LDA + c] = v;
    }
    __syncthreads();

    float acc[16][CPL];
#pragma unroll
    for (int r = 0; r < 16; r++)
#pragma unroll
        for (int j = 0; j < CPL; j++) acc[r][j] = 0.f;

    const float* pA = sA + (wid * 16) * LDA;
#pragma unroll 2
    for (int k = 0; k < 64; k += 4) {
        float4 w[CPL];
#pragma unroll
        for (int j = 0; j < CPL; j++) w[j] = *(const float4*)&sW[(lane + 32 * j) * LDA + k];
#pragma unroll
        for (int r = 0; r < 16; r++) {
            float4 a = *(const float4*)&pA[r * LDA + k];
#pragma unroll
            for (int j = 0; j < CPL; j++) {
                acc[r][j] = fmaf(a.x, w[j].x, acc[r][j]);
                acc[r][j] = fmaf(a.y, w[j].y, acc[r][j]);
                acc[r][j] = fmaf(a.z, w[j].z, acc[r][j]);
                acc[r][j] = fmaf(a.w, w[j].w, acc[r][j]);
            }
        }
    }

    int rbase = row0 + wid * 16;
    float s[CPL], q[CPL];
#pragma unroll
    for (int j = 0; j < CPL; j++) { s[j] = 0.f; q[j] = 0.f; }
#pragma unroll
    for (int r = 0; r < 16; r++) {
        if (rbase + r < nrows) {
#pragma unroll
            for (int j = 0; j < CPL; j++) {
                float v = acc[r][j];
                Y[(size_t)(rbase + r) * COUT + lane + 32 * j] = v;
                if (STATS) { s[j] += v; q[j] += v * v; }
            }
        }
    }
    if (STATS) {
#pragma unroll
        for (int j = 0; j < CPL; j++) {
            atomicAdd(&sS[lane + 32 * j], s[j]);
            atomicAdd(&sS[COUT + lane + 32 * j], q[j]);
        }
        __syncthreads();
        if (tid < COUT) {
            atomicAdd(&accout[tid], (double)sS[tid]);
            atomicAdd(&accout[COUT + tid], (double)sS[COUT + tid]);
        }
    }
}

// =====================================================================
// NARROW layers: COUT small (8, 20). Lane = row (strided conflict-free
// A reads), W reads warp-uniform broadcast. 256 rows / block.
// Optionally accumulates INPUT channel stats during staging (raw X;
// used with AFF=false for the lv/stage0 stats fused into proj).
// =====================================================================
template <int CIN, int COUT, bool AFF, bool STATS>
__global__ void __launch_bounds__(256)
layer_narrow_kernel(const float* __restrict__ X, const float* __restrict__ W,
                    const float* __restrict__ scale, const float* __restrict__ shift,
                    float* __restrict__ Y, double* __restrict__ accout, int nrows) {
    constexpr int LDA = CIN + 4, TRN = 256;
    extern __shared__ float sm[];
    float* sA = sm;                    // [TRN][LDA]
    float* sW = sA + TRN * LDA;        // [COUT][LDA]
    float* sS = sW + COUT * LDA;       // [2*CIN]
    int tid = threadIdx.x, lane = tid & 31, wid = tid >> 5;
    int row0 = blockIdx.x * TRN;

    for (int i = tid * 4; i < COUT * CIN; i += 1024) {
        int o = i / CIN, c = i % CIN;
        *(float4*)&sW[o * LDA + c] = *(const float4*)&W[i];
    }
    if (STATS) {
        for (int i = tid; i < 2 * CIN; i += 256) sS[i] = 0.f;
    }

    int c0 = (tid * 4) % CIN;          // fixed per thread (1024 % CIN == 0)
    float4 sc4, sh4;
    if (AFF) { sc4 = *(const float4*)&scale[c0]; sh4 = *(const float4*)&shift[c0]; }
    float4 ls = make_float4(0.f, 0.f, 0.f, 0.f);
    float4 lq = make_float4(0.f, 0.f, 0.f, 0.f);
    for (int i = tid * 4; i < TRN * CIN; i += 1024) {
        int r = i / CIN, c = i % CIN;
        float4 v = make_float4(0.f, 0.f, 0.f, 0.f);
        if (row0 + r < nrows) v = *(const float4*)&X[(size_t)(row0 + r) * CIN + c];
        if (STATS) {
            ls.x += v.x; ls.y += v.y; ls.z += v.z; ls.w += v.w;
            lq.x += v.x * v.x; lq.y += v.y * v.y; lq.z += v.z * v.z; lq.w += v.w * v.w;
        }
        if (AFF) {
            v.x = fmaxf(fmaf(v.x, sc4.x, sh4.x), 0.f);
            v.y = fmaxf(fmaf(v.y, sc4.y, sh4.y), 0.f);
            v.z = fmaxf(fmaf(v.z, sc4.z, sh4.z), 0.f);
            v.w = fmaxf(fmaf(v.w, sc4.w, sh4.w), 0.f);
        }
        *(float4*)&sA[r * LDA + c] = v;
    }
    if (STATS) {
        atomicAdd(&sS[c0 + 0], ls.x); atomicAdd(&sS[c0 + 1], ls.y);
        atomicAdd(&sS[c0 + 2], ls.z); atomicAdd(&sS[c0 + 3], ls.w);
        atomicAdd(&sS[CIN + c0 + 0], lq.x); atomicAdd(&sS[CIN + c0 + 1], lq.y);
        atomicAdd(&sS[CIN + c0 + 2], lq.z); atomicAdd(&sS[CIN + c0 + 3], lq.w);
    }
    __syncthreads();

    int r = wid * 32 + lane;
    float acc[COUT];
#pragma unroll
    for (int o = 0; o < COUT; o++) acc[o] = 0.f;

    const float* pA = sA + r * LDA;
#pragma unroll 2
    for (int k = 0; k < CIN; k += 4) {
        float4 a = *(const float4*)&pA[k];
#pragma unroll
        for (int o = 0; o < COUT; o++) {
            float4 w = *(const float4*)&sW[o * LDA + k];
            acc[o] = fmaf(a.x, w.x, acc[o]);
            acc[o] = fmaf(a.y, w.y, acc[o]);
            acc[o] = fmaf(a.z, w.z, acc[o]);
            acc[o] = fmaf(a.w, w.w, acc[o]);
        }
    }
    if (row0 + r < nrows) {
        float4* yo = (float4*)&Y[(size_t)(row0 + r) * COUT];
#pragma unroll
        for (int o = 0; o < COUT; o += 4)
            yo[o >> 2] = make_float4(acc[o], acc[o + 1], acc[o + 2], acc[o + 3]);
    }
    if (STATS) {
        __syncthreads();
        if (tid < CIN) {
            atomicAdd(&accout[tid], (double)sS[tid]);
            atomicAdd(&accout[CIN + tid], (double)sS[CIN + tid]);
        }
    }
}

// ---------------- per-position epilogue ----------------
__global__ void final_kernel(const int* __restrict__ idx, const float* __restrict__ bary,
                             const float* __restrict__ x3, const float* __restrict__ proj,
                             const float* __restrict__ gamma, const float* __restrict__ beta,
                             const float* __restrict__ dWw, const float* __restrict__ dWb,
                             const float* __restrict__ clsb, float* __restrict__ out, int npos) {
    int p = blockIdx.x * blockDim.x + threadIdx.x;
    if (p >= npos) return;

    int4   vi = ((const int4*)idx)[p];
    float4 vb = ((const float4*)bary)[p];
    int   ivs[4] = {vi.x, vi.y, vi.z, vi.w};
    float bb[4]  = {vb.x, vb.y, vb.z, vb.w};

    float row[4][9];
#pragma unroll
    for (int v = 0; v < 4; v++) {
        const float4* xp = (const float4*)(x3 + (size_t)ivs[v] * 8);
        float4 a = __ldg(xp);
        float4 b = __ldg(xp + 1);
        row[v][0] = a.x; row[v][1] = a.y; row[v][2] = a.z; row[v][3] = a.w;
        row[v][4] = b.x; row[v][5] = b.y; row[v][6] = b.z; row[v][7] = b.w;
        row[v][8] = bb[v];
    }

    float wv[4];
    float db = __ldg(dWb);
#pragma unroll
    for (int v = 0; v < 4; v++) wv[v] = db;

#pragma unroll
    for (int j = 0; j < 9; j++) {
        float m   = fmaxf(fmaxf(row[0][j], row[1][j]), fmaxf(row[2][j], row[3][j]));
        float off = fmaf(__ldg(&gamma[j]), m, __ldg(&beta[j]));
        float dw  = __ldg(&dWw[j]);
#pragma unroll
        for (int v = 0; v < 4; v++) wv[v] = fmaf(row[v][j] - off, dw, wv[v]);
    }
#pragma unroll
    for (int v = 0; v < 4; v++) wv[v] += bb[v];

    float o[20];
#pragma unroll
    for (int c = 0; c < 20; c++) o[c] = __ldg(&clsb[c]);

#pragma unroll
    for (int v = 0; v < 4; v++) {
        const float4* pr = (const float4*)(proj + (size_t)ivs[v] * 20);
        float w = wv[v];
#pragma unroll
        for (int k = 0; k < 5; k++) {
            float4 q = __ldg(pr + k);
            o[4 * k + 0] = fmaf(w, q.x, o[4 * k + 0]);
            o[4 * k + 1] = fmaf(w, q.y, o[4 * k + 1]);
            o[4 * k + 2] = fmaf(w, q.z, o[4 * k + 2]);
            o[4 * k + 3] = fmaf(w, q.w, o[4 * k + 3]);
        }
    }

    float4* op = (float4*)(out + (size_t)p * 20);
#pragma unroll
    for (int k = 0; k < 5; k++)
        op[k] = make_float4(o[4 * k], o[4 * k + 1], o[4 * k + 2], o[4 * k + 3]);
}

// ---------------- launch ----------------
extern "C" void kernel_launch(void* const* d_in, const int* in_sizes, int n_in,
                              void* d_out, int out_size) {
    const float* lv    = (const float*)d_in[0];
    const int*   idx   = (const int*)d_in[2];
    const float* bary  = (const float*)d_in[3];
    const float* gn0_w = (const float*)d_in[4];
    const float* gn0_b = (const float*)d_in[5];
    const float* W0    = (const float*)d_in[6];
    const float* gn1_w = (const float*)d_in[7];
    const float* gn1_b = (const float*)d_in[8];
    const float* W1    = (const float*)d_in[9];
    const float* gn2_w = (const float*)d_in[10];
    const float* gn2_b = (const float*)d_in[11];
    const float* W2    = (const float*)d_in[12];
    const float* gamma = (const float*)d_in[13];
    const float* beta  = (const float*)d_in[14];
    const float* dW_W  = (const float*)d_in[15];
    const float* dW_b  = (const float*)d_in[16];
    const float* clsW  = (const float*)d_in[17];
    const float* clsb  = (const float*)d_in[18];
    float* out = (float*)d_out;

    float*  x1;   cudaGetSymbolAddress((void**)&x1,   g_x1);
    float*  x2;   cudaGetSymbolAddress((void**)&x2,   g_x2);
    float*  x3;   cudaGetSymbolAddress((void**)&x3,   g_x3);
    float*  proj; cudaGetSymbolAddress((void**)&proj, g_proj);
    double* acc;  cudaGetSymbolAddress((void**)&acc,  g_acc);
    float*  scl;  cudaGetSymbolAddress((void**)&scl,  g_scale);
    float*  shf;  cudaGetSymbolAddress((void**)&shf,  g_shift);

    // dynamic shared sizes (bytes)
    const int smW0 = (128 * 68 + 64 * 68 + 128) * 4;   // 52736
    const int smW1 = (128 * 68 + 32 * 68 + 64) * 4;    // 43776
    const int smP  = (256 * 68 + 20 * 68 + 128) * 4;   // 75584
    const int smL2 = (256 * 36 + 8 * 36 + 64) * 4;     // 38272

    cudaFuncSetAttribute((const void*)layer_wide_kernel<2, true>,
                         cudaFuncAttributeMaxDynamicSharedMemorySize, smW0);
    cudaFuncSetAttribute((const void*)layer_wide_kernel<1, true>,
                         cudaFuncAttributeMaxDynamicSharedMemorySize, smW1);
    cudaFuncSetAttribute((const void*)layer_narrow_kernel<64, 20, false, true>,
                         cudaFuncAttributeMaxDynamicSharedMemorySize, smP);
    cudaFuncSetAttribute((const void*)layer_narrow_kernel<32, 8, true, false>,
                         cudaFuncAttributeMaxDynamicSharedMemorySize, smL2);

    const int gw = (NVERT + 127) / 128;   // 2344
    const int gn = (NVERT + 255) / 256;   // 1172

    init_acc_kernel<<<1, 320>>>();

    // proj = lv @ cls_W^T, with fused stage-0 (lv) channel stats
    layer_narrow_kernel<64, 20, false, true><<<gn, 256, smP>>>(
        lv, clsW, nullptr, nullptr, proj, acc, NVERT);
    finalize_kernel<64><<<1, 64>>>(acc, gn0_w, gn0_b, scl, shf, NVERT);

    // layer0: GN0+ReLU fused on load, GEMM 64->64, fused x1 stats
    layer_wide_kernel<2, true><<<gw, 256, smW0>>>(lv, W0, scl, shf, x1, acc + 128, NVERT);
    finalize_kernel<64><<<1, 64>>>(acc + 128, gn1_w, gn1_b, scl + 64, shf + 64, NVERT);

    // layer1: GN1+ReLU fused, GEMM 64->32, fused x2 stats
    layer_wide_kernel<1, true><<<gw, 256, smW1>>>(x1, W1, scl + 64, shf + 64, x2, acc + 256, NVERT);
    finalize_kernel<32><<<1, 32>>>(acc + 256, gn2_w, gn2_b, scl + 128, shf + 128, NVERT);

    // layer2: GN2+ReLU fused, GEMM 32->8
    layer_narrow_kernel<32, 8, true, false><<<gn, 256, smL2>>>(
        x2, W2, scl + 128, shf + 128, x3, nullptr, NVERT);

    // per-position gather + simplex norm + delta weights + classify
    final_kernel<<<(NPOS + 255) / 256, 256>>>(idx, bary, x3, proj, gamma, beta,
                                              dW_W, dW_b, clsb, out, NPOS);
}

// round 8
// speedup vs baseline: 2.7363x; 1.1412x over previous
#include <cuda_runtime.h>
#include <math.h>
#include <stdint.h>

#define NVERT 300000
#define NPOS  500000

// ---------------- device scratch (no allocs allowed) ----------------
__device__ float  g_x1[NVERT * 64];
__device__ float  g_x2[NVERT * 32];
__device__ float  g_x3[NVERT * 8];
__device__ float  g_proj[NVERT * 20];
__device__ double g_acc[320];          // lv @0, x1 @128, x2 @256 (sum|sumsq)
__device__ float  g_scale[160];
__device__ float  g_shift[160];

__global__ void init_acc_kernel() {
    int i = threadIdx.x;
    if (i < 320) g_acc[i] = 0.0;
}

// ---------------- stats -> per-channel affine (GN folded) ----------------
template <int C>
__global__ void finalize_kernel(const double* __restrict__ acc,
                                const float* __restrict__ w, const float* __restrict__ b,
                                float* __restrict__ scale, float* __restrict__ shift, int nrows) {
    int c = threadIdx.x;
    if (c >= C) return;
    constexpr int CPG = C / 32;
    int g = c / CPG;
    double s = 0.0, q = 0.0;
#pragma unroll
    for (int j = 0; j < CPG; j++) {
        s += acc[g * CPG + j];
        q += acc[C + g * CPG + j];
    }
    double n   = (double)nrows * (double)CPG;
    double mu  = s / n;
    double var = q / n - mu * mu;
    float  rs  = (float)(1.0 / sqrt(var + 1e-5));
    float  sc  = w[c] * rs;
    scale[c] = sc;
    shift[c] = b[c] - (float)mu * sc;
}

// ---------------- tf32 mma helpers (legacy mma.sync, sm_80+ PTX) ----------------
__device__ __forceinline__ uint32_t f2tf32(float x) {
    uint32_t r;
    asm("cvt.rna.tf32.f32 %0, %1;" : "=r"(r) : "f"(x));
    return r;
}
__device__ __forceinline__ void mma8(float* c, const uint32_t* a, const uint32_t* b) {
    asm volatile("mma.sync.aligned.m16n8k8.row.col.f32.tf32.tf32.f32 "
                 "{%0,%1,%2,%3}, {%4,%5,%6,%7}, {%8,%9}, {%0,%1,%2,%3};"
                 : "+f"(c[0]), "+f"(c[1]), "+f"(c[2]), "+f"(c[3])
                 : "r"(a[0]), "r"(a[1]), "r"(a[2]), "r"(a[3]), "r"(b[0]), "r"(b[1]));
}

// =====================================================================
// tf32 tensor-core GEMM: Y[r,o] = sum_k f(X[r,k]) * W[o,k], M=128/CTA.
// f = relu(x*scale+shift) if AFF. 3-term split-tf32 (fp32-accurate):
// D = ah*bh + ah*bl + al*bh  (drops only the eps^2 al*bl term).
// INSTATS: channel stats of raw X fused into staging.
// OUTSTATS: channel stats of Y fused via fragment shfl-reduce.
// =====================================================================
template <int CIN, int NOUT, int NPAD, bool AFF, bool INSTATS, bool OUTSTATS>
__global__ void __launch_bounds__(256)
mgemm_kernel(const float* __restrict__ X, const float* __restrict__ W,
             const float* __restrict__ scale, const float* __restrict__ shift,
             float* __restrict__ Y, double* __restrict__ accout, int nrows) {
    constexpr int M = 128, LDA = CIN + 4, NT = NPAD / 8;
    extern __shared__ float sm[];
    float* sA = sm;                    // [M][LDA]
    float* sW = sA + M * LDA;          // [NPAD][LDA]
    float* sS = sW + NPAD * LDA;       // [256]

    int tid = threadIdx.x, lane = tid & 31, wid = tid >> 5;
    int g = lane >> 2, t = lane & 3;
    int row0 = blockIdx.x * M;

    if (INSTATS || OUTSTATS) sS[tid] = 0.f;

    // ---- stage W (zero-pad rows >= NOUT) ----
    for (int i = tid * 4; i < NPAD * CIN; i += 1024) {
        int o = i / CIN, c = i % CIN;
        float4 w = make_float4(0.f, 0.f, 0.f, 0.f);
        if (o < NOUT) w = *(const float4*)&W[o * CIN + c];
        *(float4*)&sW[o * LDA + c] = w;
    }

    // ---- stage A (fused affine+relu; optional raw input stats) ----
    int c0 = (tid * 4) % CIN;          // fixed per thread (1024 % CIN == 0)
    float4 sc4, sh4;
    if (AFF) { sc4 = *(const float4*)&scale[c0]; sh4 = *(const float4*)&shift[c0]; }
    float4 ls = make_float4(0.f, 0.f, 0.f, 0.f);
    float4 lq = make_float4(0.f, 0.f, 0.f, 0.f);
    for (int i = tid * 4; i < M * CIN; i += 1024) {
        int r = i / CIN, c = i % CIN;
        float4 v = make_float4(0.f, 0.f, 0.f, 0.f);
        if (row0 + r < nrows) v = *(const float4*)&X[(size_t)(row0 + r) * CIN + c];
        if (INSTATS) {
            ls.x += v.x; ls.y += v.y; ls.z += v.z; ls.w += v.w;
            lq.x += v.x * v.x; lq.y += v.y * v.y; lq.z += v.z * v.z; lq.w += v.w * v.w;
        }
        if (AFF) {
            v.x = fmaxf(fmaf(v.x, sc4.x, sh4.x), 0.f);
            v.y = fmaxf(fmaf(v.y, sc4.y, sh4.y), 0.f);
            v.z = fmaxf(fmaf(v.z, sc4.z, sh4.z), 0.f);
            v.w = fmaxf(fmaf(v.w, sc4.w, sh4.w), 0.f);
        }
        *(float4*)&sA[r * LDA + c] = v;
    }
    if (INSTATS) {
        atomicAdd(&sS[c0 + 0], ls.x); atomicAdd(&sS[c0 + 1], ls.y);
        atomicAdd(&sS[c0 + 2], ls.z); atomicAdd(&sS[c0 + 3], ls.w);
        atomicAdd(&sS[128 + c0 + 0], lq.x); atomicAdd(&sS[128 + c0 + 1], lq.y);
        atomicAdd(&sS[128 + c0 + 2], lq.z); atomicAdd(&sS[128 + c0 + 3], lq.w);
    }
    __syncthreads();
    if (INSTATS && tid < CIN) {
        atomicAdd(&accout[tid], (double)sS[tid]);
        atomicAdd(&accout[CIN + tid], (double)sS[128 + tid]);
    }

    // ---- mma compute: warp owns rows [16*wid, 16*wid+16) ----
    int ar = wid * 16 + g;
    float acc[NT][4];
#pragma unroll
    for (int n = 0; n < NT; n++)
#pragma unroll
        for (int j = 0; j < 4; j++) acc[n][j] = 0.f;

#pragma unroll
    for (int k0 = 0; k0 < CIN; k0 += 8) {
        float af[4];
        af[0] = sA[ar * LDA + k0 + t];
        af[1] = sA[(ar + 8) * LDA + k0 + t];
        af[2] = sA[ar * LDA + k0 + t + 4];
        af[3] = sA[(ar + 8) * LDA + k0 + t + 4];
        uint32_t ah[4], al[4];
#pragma unroll
        for (int j = 0; j < 4; j++) {
            ah[j] = f2tf32(af[j]);
            al[j] = f2tf32(af[j] - __uint_as_float(ah[j]));
        }
#pragma unroll
        for (int n = 0; n < NT; n++) {
            float bf0 = sW[(n * 8 + g) * LDA + k0 + t];
            float bf1 = sW[(n * 8 + g) * LDA + k0 + t + 4];
            uint32_t bh[2], bl[2];
            bh[0] = f2tf32(bf0); bh[1] = f2tf32(bf1);
            bl[0] = f2tf32(bf0 - __uint_as_float(bh[0]));
            bl[1] = f2tf32(bf1 - __uint_as_float(bh[1]));
            mma8(acc[n], ah, bh);
            mma8(acc[n], ah, bl);
            mma8(acc[n], al, bh);
        }
    }

    // ---- store (fragment layout: c0/c1 at (row, 2t), c2/c3 at (row+8, 2t)) ----
    int r0 = row0 + wid * 16 + g;
    bool v0 = r0 < nrows, v1 = (r0 + 8) < nrows;
#pragma unroll
    for (int n = 0; n < NT; n++) {
        int col = n * 8 + 2 * t;
        if (col < NOUT) {
            if (v0) *(float2*)&Y[(size_t)r0 * NOUT + col]       = make_float2(acc[n][0], acc[n][1]);
            if (v1) *(float2*)&Y[(size_t)(r0 + 8) * NOUT + col] = make_float2(acc[n][2], acc[n][3]);
        }
    }

    // ---- fused output-channel stats via shfl reduce over fragment rows ----
    if (OUTSTATS) {
#pragma unroll
        for (int n = 0; n < NT; n++) {
            float e0 = v0 ? acc[n][0] : 0.f, o0 = v0 ? acc[n][1] : 0.f;
            float e1 = v1 ? acc[n][2] : 0.f, o1 = v1 ? acc[n][3] : 0.f;
            float se = e0 + e1, qe = e0 * e0 + e1 * e1;
            float so = o0 + o1, qo = o0 * o0 + o1 * o1;
#pragma unroll
            for (int off = 4; off < 32; off <<= 1) {
                se += __shfl_xor_sync(0xffffffffu, se, off);
                qe += __shfl_xor_sync(0xffffffffu, qe, off);
                so += __shfl_xor_sync(0xffffffffu, so, off);
                qo += __shfl_xor_sync(0xffffffffu, qo, off);
            }
            if (g == 0) {
                int col = n * 8 + 2 * t;
                atomicAdd(&sS[col], se);       atomicAdd(&sS[col + 1], so);
                atomicAdd(&sS[128 + col], qe); atomicAdd(&sS[128 + col + 1], qo);
            }
        }
        __syncthreads();
        if (tid < NOUT) {
            atomicAdd(&accout[tid], (double)sS[tid]);
            atomicAdd(&accout[NOUT + tid], (double)sS[128 + tid]);
        }
    }
}

// ---------------- per-position epilogue ----------------
__global__ void final_kernel(const int* __restrict__ idx, const float* __restrict__ bary,
                             const float* __restrict__ x3, const float* __restrict__ proj,
                             const float* __restrict__ gamma, const float* __restrict__ beta,
                             const float* __restrict__ dWw, const float* __restrict__ dWb,
                             const float* __restrict__ clsb, float* __restrict__ out, int npos) {
    int p = blockIdx.x * blockDim.x + threadIdx.x;
    if (p >= npos) return;

    int4   vi = ((const int4*)idx)[p];
    float4 vb = ((const float4*)bary)[p];
    int   ivs[4] = {vi.x, vi.y, vi.z, vi.w};
    float bb[4]  = {vb.x, vb.y, vb.z, vb.w};

    float row[4][9];
#pragma unroll
    for (int v = 0; v < 4; v++) {
        const float4* xp = (const float4*)(x3 + (size_t)ivs[v] * 8);
        float4 a = __ldg(xp);
        float4 b = __ldg(xp + 1);
        row[v][0] = a.x; row[v][1] = a.y; row[v][2] = a.z; row[v][3] = a.w;
        row[v][4] = b.x; row[v][5] = b.y; row[v][6] = b.z; row[v][7] = b.w;
        row[v][8] = bb[v];
    }

    float wv[4];
    float db = __ldg(dWb);
#pragma unroll
    for (int v = 0; v < 4; v++) wv[v] = db;

#pragma unroll
    for (int j = 0; j < 9; j++) {
        float m   = fmaxf(fmaxf(row[0][j], row[1][j]), fmaxf(row[2][j], row[3][j]));
        float off = fmaf(__ldg(&gamma[j]), m, __ldg(&beta[j]));
        float dw  = __ldg(&dWw[j]);
#pragma unroll
        for (int v = 0; v < 4; v++) wv[v] = fmaf(row[v][j] - off, dw, wv[v]);
    }
#pragma unroll
    for (int v = 0; v < 4; v++) wv[v] += bb[v];

    float o[20];
#pragma unroll
    for (int c = 0; c < 20; c++) o[c] = __ldg(&clsb[c]);

#pragma unroll
    for (int v = 0; v < 4; v++) {
        const float4* pr = (const float4*)(proj + (size_t)ivs[v] * 20);
        float w = wv[v];
#pragma unroll
        for (int k = 0; k < 5; k++) {
            float4 q = __ldg(pr + k);
            o[4 * k + 0] = fmaf(w, q.x, o[4 * k + 0]);
            o[4 * k + 1] = fmaf(w, q.y, o[4 * k + 1]);
            o[4 * k + 2] = fmaf(w, q.z, o[4 * k + 2]);
            o[4 * k + 3] = fmaf(w, q.w, o[4 * k + 3]);
        }
    }

    float4* op = (float4*)(out + (size_t)p * 20);
#pragma unroll
    for (int k = 0; k < 5; k++)
        op[k] = make_float4(o[4 * k], o[4 * k + 1], o[4 * k + 2], o[4 * k + 3]);
}

// ---------------- launch ----------------
extern "C" void kernel_launch(void* const* d_in, const int* in_sizes, int n_in,
                              void* d_out, int out_size) {
    const float* lv    = (const float*)d_in[0];
    const int*   idx   = (const int*)d_in[2];
    const float* bary  = (const float*)d_in[3];
    const float* gn0_w = (const float*)d_in[4];
    const float* gn0_b = (const float*)d_in[5];
    const float* W0    = (const float*)d_in[6];
    const float* gn1_w = (const float*)d_in[7];
    const float* gn1_b = (const float*)d_in[8];
    const float* W1    = (const float*)d_in[9];
    const float* gn2_w = (const float*)d_in[10];
    const float* gn2_b = (const float*)d_in[11];
    const float* W2    = (const float*)d_in[12];
    const float* gamma = (const float*)d_in[13];
    const float* beta  = (const float*)d_in[14];
    const float* dW_W  = (const float*)d_in[15];
    const float* dW_b  = (const float*)d_in[16];
    const float* clsW  = (const float*)d_in[17];
    const float* clsb  = (const float*)d_in[18];
    float* out = (float*)d_out;

    float*  x1;   cudaGetSymbolAddress((void**)&x1,   g_x1);
    float*  x2;   cudaGetSymbolAddress((void**)&x2,   g_x2);
    float*  x3;   cudaGetSymbolAddress((void**)&x3,   g_x3);
    float*  proj; cudaGetSymbolAddress((void**)&proj, g_proj);
    double* acc;  cudaGetSymbolAddress((void**)&acc,  g_acc);
    float*  scl;  cudaGetSymbolAddress((void**)&scl,  g_scale);
    float*  shf;  cudaGetSymbolAddress((void**)&shf,  g_shift);

    // dynamic smem bytes: (128*LDA + NPAD*LDA + 256) * 4
    const int smP  = (128 * 68 + 24 * 68 + 256) * 4;   // 42368
    const int smL0 = (128 * 68 + 64 * 68 + 256) * 4;   // 53248
    const int smL1 = (128 * 68 + 32 * 68 + 256) * 4;   // 44544
    const int smL2 = (128 * 36 +  8 * 36 + 256) * 4;   // 20608

    cudaFuncSetAttribute((const void*)mgemm_kernel<64, 20, 24, false, true,  false>,
                         cudaFuncAttributeMaxDynamicSharedMemorySize, smP);
    cudaFuncSetAttribute((const void*)mgemm_kernel<64, 64, 64, true,  false, true >,
                         cudaFuncAttributeMaxDynamicSharedMemorySize, smL0);
    cudaFuncSetAttribute((const void*)mgemm_kernel<64, 32, 32, true,  false, true >,
                         cudaFuncAttributeMaxDynamicSharedMemorySize, smL1);
    cudaFuncSetAttribute((const void*)mgemm_kernel<32, 8,  8,  true,  false, false>,
                         cudaFuncAttributeMaxDynamicSharedMemorySize, smL2);

    const int gt = (NVERT + 127) / 128;   // 2344

    init_acc_kernel<<<1, 320>>>();

    // proj = lv @ cls_W^T  (+ fused lv stats for GN0)
    mgemm_kernel<64, 20, 24, false, true, false><<<gt, 256, smP>>>(
        lv, clsW, nullptr, nullptr, proj, acc, NVERT);
    finalize_kernel<64><<<1, 64>>>(acc, gn0_w, gn0_b, scl, shf, NVERT);

    // layer0: GN0+ReLU fused, 64->64 (+x1 stats)
    mgemm_kernel<64, 64, 64, true, false, true><<<gt, 256, smL0>>>(
        lv, W0, scl, shf, x1, acc + 128, NVERT);
    finalize_kernel<64><<<1, 64>>>(acc + 128, gn1_w, gn1_b, scl + 64, shf + 64, NVERT);

    // layer1: GN1+ReLU fused, 64->32 (+x2 stats)
    mgemm_kernel<64, 32, 32, true, false, true><<<gt, 256, smL1>>>(
        x1, W1, scl + 64, shf + 64, x2, acc + 256, NVERT);
    finalize_kernel<32><<<1, 32>>>(acc + 256, gn2_w, gn2_b, scl + 128, shf + 128, NVERT);

    // layer2: GN2+ReLU fused, 32->8
    mgemm_kernel<32, 8, 8, true, false, false><<<gt, 256, smL2>>>(
        x2, W2, scl + 128, shf + 128, x3, nullptr, NVERT);

    // per-position gather + simplex norm + delta weights + classify
    final_kernel<<<(NPOS + 255) / 256, 256>>>(idx, bary, x3, proj, gamma, beta,
                                              dW_W, dW_b, clsb, out, NPOS);
}